// round 15
// baseline (speedup 1.0000x reference)
#include <cuda_runtime.h>
#include <math_constants.h>

#define B_ 32
#define H_ 8
#define L_ 2048
#define E_ 64

#define NTHREADS 128
#define ROWS 32          // rows per block
#define RPC  16          // row-pairs per block
#define SQ 132           // q region stride per rp: 32 chunks + 1 pad chunk (33 == 1 mod 8); corr aliases
#define SK 132           // k region stride (33 chunks == 1 mod 8 -> LDK broadcasts hit distinct quads)
#define SV 68            // v row stride (17 chunks == 1 mod 8)

// chunk swizzle: conflict-free for store pattern (8g+4par+u) and FIR octet pattern ((C+4s)&31)
__device__ __forceinline__ int sw(int c) { return c ^ ((c >> 2) & 7); }

// packed f32x2 fma: d = a*b + d (lo = even row, hi = odd row)
__device__ __forceinline__ void ffma2(unsigned long long& d,
                                      unsigned long long a,
                                      unsigned long long b) {
    asm("fma.rn.f32x2 %0, %1, %2, %0;" : "+l"(d) : "l"(a), "l"(b));
}

// monotone order-preserving float->uint flip (IEEE total order for finite values)
__device__ __forceinline__ unsigned int fflip(float v) {
    unsigned int fb = __float_as_uint(v);
    return fb ^ ((unsigned int)((int)fb >> 31) | 0x80000000u);
}
__device__ __forceinline__ float funflip(unsigned int u) {
    unsigned int fb = (u & 0x80000000u) ? (u ^ 0x80000000u) : ~u;
    return __uint_as_float(fb);
}

// AutoCorrelation (Autoformer):
//   corr[b,h,l,d] = sum_e q[b,h,l,(e+d)%64] * k[b,h,l,e]
//   top-4 over d, softmax, V_out[e] = sum_i p_i * v[(e+d_i)%64]
//   outputs: V (B,H,L,E) then corr transposed to (B,E,H,L)
__global__ __launch_bounds__(NTHREADS, 7)
void ac_kernel(const float* __restrict__ Q, const float* __restrict__ Kk,
               const float* __restrict__ Vv, float* __restrict__ outV,
               float* __restrict__ outC)
{
    __shared__ __align__(16) float s_qq[RPC * SQ];   // interleaved (even,odd) q pairs, swizzled
    __shared__ __align__(16) float s_kk[RPC * SK];   // interleaved k pairs, swizzled
    __shared__ __align__(16) float s_v [ROWS * SV];  // v, plain

    const int t     = threadIdx.x;
    const int lane  = t & 31;
    const int w     = t >> 5;
    const int ltile = blockIdx.x;
    const int bh    = blockIdx.y;
    const int h     = bh & (H_ - 1);
    const int b     = bh >> 3;
    const int l0    = ltile * ROWS;

    // ---------------- load phase (sequenced v -> q -> k to cap registers) ----
    {
        const int g   = lane & 3;          // 4 col-groups of 16 floats
        const int rr  = lane >> 2;         // 8 local rows per warp
        const int par = rr & 1;
        const int rl  = 8 * w + rr;
        const int rpg = rl >> 1;
        const size_t rowbase = ((size_t)bh * L_ + l0 + rl) * (size_t)E_;
        const int col = 16 * g;
        float* qrow = s_qq + rpg * SQ;
        float* krow = s_kk + rpg * SK;

        // ---- v: straight copy (quad = (rr + 4g + u) mod 8 -> 4-wf floor) ----
        {
            float* vr = s_v + rl * SV;
            #pragma unroll
            for (int u = 0; u < 4; ++u) {
                float4 vv4 = *(const float4*)(Vv + rowbase + col + 4*u);
                *(float4*)(vr + col + 4*u) = vv4;
            }
        }

        // ---- q: load, parity-exchange (lane^4), interleaved swizzled store --
        {
            float qa[16];
            #pragma unroll
            for (int u = 0; u < 4; ++u)
                *(float4*)(qa + 4*u) = *(const float4*)(Q + rowbase + col + 4*u);
            float qr[8];
            #pragma unroll
            for (int j = 0; j < 8; ++j) {
                float qs = par ? qa[j] : qa[8 + j];
                qr[j] = __shfl_xor_sync(0xffffffffu, qs, 4);
            }
            #pragma unroll
            for (int u = 0; u < 4; ++u) {
                const int c   = 8*g + 4*par + u;
                const int off = 4 * sw(c);
                float4 fq;
                if (!par) fq = make_float4(qa[2*u], qr[2*u], qa[2*u+1], qr[2*u+1]);
                else      fq = make_float4(qr[2*u], qa[8+2*u], qr[2*u+1], qa[8+2*u+1]);
                *(float4*)(qrow + off) = fq;
            }
        }

        // ---- k: same dance ---------------------------------------------------
        {
            float ka[16];
            #pragma unroll
            for (int u = 0; u < 4; ++u)
                *(float4*)(ka + 4*u) = *(const float4*)(Kk + rowbase + col + 4*u);
            float kr[8];
            #pragma unroll
            for (int j = 0; j < 8; ++j) {
                float ks = par ? ka[j] : ka[8 + j];
                kr[j] = __shfl_xor_sync(0xffffffffu, ks, 4);
            }
            #pragma unroll
            for (int u = 0; u < 4; ++u) {
                const int c   = 8*g + 4*par + u;
                const int off = 4 * sw(c);
                float4 fk;
                if (!par) fk = make_float4(ka[2*u], kr[2*u], ka[2*u+1], kr[2*u+1]);
                else      fk = make_float4(kr[2*u], ka[8+2*u], kr[2*u+1], ka[8+2*u+1]);
                *(float4*)(krow + off) = fk;
            }
        }
    }
    __syncwarp();

    // ---------------- FIR correlation: 8 delays/lane, f32x2, 2 rows/lane -----
    const int s   = lane & 7;            // delay-octet sub-lane
    const int oct = lane >> 3;
    const int rp  = 4 * w + oct;         // row-pair owned by this octet
    const float* qq = s_qq + rp * SQ;
    const float* kk = s_kk + rp * SK;
    const int cb0 = 4 * s;               // chunk of element d0 = 8s

    #define LDQ(c) (*(const ulonglong2*)(qq + 4 * sw((c) & 31)))
    #define LDK(c) (*(const ulonglong2*)(kk + 4 * sw(c)))

    unsigned long long W[12], acc[8];
    #pragma unroll
    for (int u = 0; u < 4; ++u) {
        ulonglong2 tv = LDQ(cb0 + u);
        W[2*u] = tv.x; W[2*u + 1] = tv.y;
    }
    #pragma unroll
    for (int j = 0; j < 8; ++j) acc[j] = 0ull;

    #pragma unroll
    for (int blk = 0; blk < 16; ++blk) {
        ulonglong2 t0 = LDQ(cb0 + 2*blk + 4);
        ulonglong2 t1 = LDQ(cb0 + 2*blk + 5);
        W[8] = t0.x; W[9] = t0.y; W[10] = t1.x; W[11] = t1.y;
        ulonglong2 ka_ = LDK(2*blk);
        ulonglong2 kb_ = LDK(2*blk + 1);
        unsigned long long kp[4] = {ka_.x, ka_.y, kb_.x, kb_.y};
        #pragma unroll
        for (int tt = 0; tt < 4; ++tt)
            #pragma unroll
            for (int j = 0; j < 8; ++j)
                ffma2(acc[j], W[tt + j], kp[tt]);
        #pragma unroll
        for (int m = 0; m < 8; ++m) W[m] = W[m + 4];
    }
    __syncwarp();   // all q reads done before aliased corr staging

    // ---------------- split accumulators; stage corr into aliased q region ---
    // word e of corr row r lives at position e ^ (4*((r>>4)&1)) within the row
    // region: de-conflicts the transposed-read epilogue (rb vs rb+4 banks).
    float ex[8], od[8];
    #pragma unroll
    for (int j = 0; j < 8; ++j) {
        float2 f = *reinterpret_cast<float2*>(&acc[j]);
        ex[j] = f.x; od[j] = f.y;
    }
    const int x4c = ((rp >> 3) & 1) << 2;   // row 2rp and 2rp+1 share r>>4
    {
        float* ce = s_qq + rp * SQ;      // corr row 2rp   : words 0..63 (perm)
        float* co = ce + 68;             // corr row 2rp+1 : words 68..131 (perm)
        *(float4*)(ce + (( 8*s     ) ^ x4c)) = make_float4(ex[0], ex[1], ex[2], ex[3]);
        *(float4*)(ce + (( 8*s + 4 ) ^ x4c)) = make_float4(ex[4], ex[5], ex[6], ex[7]);
        *(float4*)(co + (( 8*s     ) ^ x4c)) = make_float4(od[0], od[1], od[2], od[3]);
        *(float4*)(co + (( 8*s + 4 ) ^ x4c)) = make_float4(od[4], od[5], od[6], od[7]);
    }

    // ---------------- top-4 + softmax + gather (64-bit packed-key argmax) ----
    // key = fflip(value) << 6 | (63 - delay): EXACT (value desc, delay asc)
    // ordering under unsigned max -- bit-identical selection to jax top_k,
    // 1x 64-bit shfl + 1x u64 max per butterfly step.
    #pragma unroll
    for (int pass = 0; pass < 2; ++pass) {
        const int rowl = 8 * w + 2 * oct + pass;

        unsigned long long kv[8];
        #pragma unroll
        for (int j = 0; j < 8; ++j) {
            float v = pass ? od[j] : ex[j];
            kv[j] = ((unsigned long long)fflip(v) << 6)
                  | (unsigned long long)(63 - (8*s + j));
        }

        float wv[4]; int wd[4];
        #pragma unroll
        for (int i = 0; i < 4; ++i) {
            unsigned long long bk = max(max(max(kv[0], kv[1]), max(kv[2], kv[3])),
                                        max(max(kv[4], kv[5]), max(kv[6], kv[7])));
            #pragma unroll
            for (int off = 4; off; off >>= 1) {
                unsigned long long ok = __shfl_xor_sync(0xffffffffu, bk, off);
                bk = max(bk, ok);
            }
            wd[i] = 63 - (int)(bk & 63ull);
            wv[i] = funflip((unsigned int)(bk >> 6));   // exact value from key
            if (i < 3) {
                #pragma unroll
                for (int j = 0; j < 8; ++j)
                    if (kv[j] == bk) kv[j] = 0ull;      // remove winner (keys unique)
            }
        }

        float p[4]; float z = 0.f;
        #pragma unroll
        for (int i = 0; i < 4; ++i) { p[i] = __expf(wv[i] - wv[0]); z += p[i]; }
        const float rz = 1.f / z;

        // gather: lane owns e = 4s..4s+3 and 4s+32..4s+35
        //   octet addresses within an instruction are (4s + const): banks
        //   stride-4, all 8 lanes distinct -> conflict-free
        const float* vrow = s_v + rowl * SV;
        float om[8] = {0.f,0.f,0.f,0.f,0.f,0.f,0.f,0.f};
        #pragma unroll
        for (int i = 0; i < 4; ++i) {
            const float pi = p[i] * rz;
            const int baseA = 4*s + wd[i];
            const int baseB = baseA + 32;
            #pragma unroll
            for (int m = 0; m < 4; ++m)
                om[m]     = fmaf(pi, vrow[(baseA + m) & 63], om[m]);
            #pragma unroll
            for (int m = 0; m < 4; ++m)
                om[4 + m] = fmaf(pi, vrow[(baseB + m) & 63], om[4 + m]);
        }
        const size_t vb = ((size_t)bh * L_ + l0 + rowl) * (size_t)E_;
        *(float4*)(outV + vb + 4*s)      = make_float4(om[0], om[1], om[2], om[3]);
        *(float4*)(outV + vb + 4*s + 32) = make_float4(om[4], om[5], om[6], om[7]);
    }

    // ---------------- transposed corr write (vectorized over l) --------------
    // outC[b,e,h,l]: thread handles 4 consecutive l via STG.128.
    // Read side applies the same e^x4 permutation used at staging; lanes rb vs
    // rb+4 hit different banks (conflict-free).
    __syncthreads();
    float* outCb = outC + (((size_t)b * E_) * H_ + h) * (size_t)L_ + l0;
    #pragma unroll
    for (int it = 0; it < 4; ++it) {
        const int idx = t + NTHREADS * it;   // 0..511
        const int e   = idx >> 3;            // 0..63
        const int rb  = idx & 7;             // r = 4*rb .. 4*rb+3
        const int r0  = 4 * rb;
        const int x4r = ((rb >> 2) & 1) << 2;   // == ((r>>4)&1)<<2 for all 4 rows
        float4 val;
        val.x = s_qq[((r0    ) >> 1) * SQ + ((r0    ) & 1) * 68 + (e ^ x4r)];
        val.y = s_qq[((r0 + 1) >> 1) * SQ + ((r0 + 1) & 1) * 68 + (e ^ x4r)];
        val.z = s_qq[((r0 + 2) >> 1) * SQ + ((r0 + 2) & 1) * 68 + (e ^ x4r)];
        val.w = s_qq[((r0 + 3) >> 1) * SQ + ((r0 + 3) & 1) * 68 + (e ^ x4r)];
        *(float4*)(outCb + (size_t)e * ((size_t)H_ * L_) + 4 * rb) = val;
    }
}

extern "C" void kernel_launch(void* const* d_in, const int* in_sizes, int n_in,
                              void* d_out, int out_size)
{
    const float* Q = (const float*)d_in[0];
    const float* K = (const float*)d_in[1];
    const float* V = (const float*)d_in[2];
    float* outV = (float*)d_out;
    float* outC = outV + (size_t)B_ * H_ * L_ * E_;

    dim3 grid(L_ / ROWS, B_ * H_);
    ac_kernel<<<grid, NTHREADS>>>(Q, K, V, outV, outC);
}

// round 17
// speedup vs baseline: 1.2858x; 1.2858x over previous
#include <cuda_runtime.h>
#include <math_constants.h>

#define B_ 32
#define H_ 8
#define L_ 2048
#define E_ 64

#define NTHREADS 128
#define ROWS 32          // rows per block
#define RPC  16          // row-pairs per block
#define SQ 132           // q region stride per rp: 32 chunks + 1 pad chunk (33 == 1 mod 8); corr aliases
#define SK 132           // k region stride (33 chunks == 1 mod 8)
#define SV 68            // v row stride (17 chunks == 1 mod 8)

// chunk swizzle: sw(4x + C) mod 8 is bijective in x for any fixed C —
// conflict-free for BOTH the store pattern (c = 4*c8 + u) and the FIR
// window pattern (c = (4*s + C) & 31)
__device__ __forceinline__ int sw(int c) { return c ^ ((c >> 2) & 7); }

// packed f32x2 fma: d = a*b + d (lo = even row, hi = odd row)
__device__ __forceinline__ void ffma2(unsigned long long& d,
                                      unsigned long long a,
                                      unsigned long long b) {
    asm("fma.rn.f32x2 %0, %1, %2, %0;" : "+l"(d) : "l"(a), "l"(b));
}

// monotone order-preserving float->uint flip (IEEE total order for finite values)
__device__ __forceinline__ unsigned int fflip(float v) {
    unsigned int fb = __float_as_uint(v);
    return fb ^ ((unsigned int)((int)fb >> 31) | 0x80000000u);
}
__device__ __forceinline__ float funflip(unsigned int u) {
    unsigned int fb = (u & 0x80000000u) ? (u ^ 0x80000000u) : ~u;
    return __uint_as_float(fb);
}

// AutoCorrelation (Autoformer):
//   corr[b,h,l,d] = sum_e q[b,h,l,(e+d)%64] * k[b,h,l,e]
//   top-4 over d, softmax, V_out[e] = sum_i p_i * v[(e+d_i)%64]
//   outputs: V (B,H,L,E) then corr transposed to (B,E,H,L)
__global__ __launch_bounds__(NTHREADS, 7)
void ac_kernel(const float* __restrict__ Q, const float* __restrict__ Kk,
               const float* __restrict__ Vv, float* __restrict__ outV,
               float* __restrict__ outC)
{
    __shared__ __align__(16) float s_qq[RPC * SQ];   // interleaved (even,odd) q pairs, swizzled
    __shared__ __align__(16) float s_kk[RPC * SK];   // interleaved k pairs, swizzled
    __shared__ __align__(16) float s_v [ROWS * SV];  // v, plain

    const int t     = threadIdx.x;
    const int lane  = t & 31;
    const int w     = t >> 5;
    const int ltile = blockIdx.x;
    const int bh    = blockIdx.y;
    const int h     = bh & (H_ - 1);
    const int b     = bh >> 3;
    const int l0    = ltile * ROWS;

    // ---------------- load phase: shuffle-free dual-row loads ----------------
    // Lane owns 8 columns of ONE row-pair; loads both rows of the pair and
    // builds the interleaved (even,odd) pairs directly in registers.
    {
        const int rpg = lane >> 3;         // row-pair within warp: 0..3
        const int c8  = lane & 7;          // col-group of 8
        const int rpb = 4 * w + rpg;       // block row-pair index
        const int rle = 2 * rpb;           // even local row
        const size_t be = ((size_t)bh * L_ + l0 + rle) * (size_t)E_;
        const size_t bo = be + E_;

        // ---- v: lane handles cols 4*c8 and 4*c8+32 of both rows
        //   STS quad = (rle + c8) mod 8 over (rpg,c8): each quad hit 4x -> 4-wf floor
        {
            float* vre = s_v + rle * SV;
            float* vro = vre + SV;
            float4 a0 = *(const float4*)(Vv + be + 4*c8);
            float4 a1 = *(const float4*)(Vv + be + 4*c8 + 32);
            float4 a2 = *(const float4*)(Vv + bo + 4*c8);
            float4 a3 = *(const float4*)(Vv + bo + 4*c8 + 32);
            *(float4*)(vre + 4*c8)      = a0;
            *(float4*)(vre + 4*c8 + 32) = a1;
            *(float4*)(vro + 4*c8)      = a2;
            *(float4*)(vro + 4*c8 + 32) = a3;
        }

        // ---- q: rows even+odd, cols 8*c8..8*c8+7 -> 4 interleaved chunks
        {
            float* qrow = s_qq + rpb * SQ;
            float4 e0 = *(const float4*)(Q + be + 8*c8);
            float4 e1 = *(const float4*)(Q + be + 8*c8 + 4);
            float4 o0 = *(const float4*)(Q + bo + 8*c8);
            float4 o1 = *(const float4*)(Q + bo + 8*c8 + 4);
            float qe[8] = {e0.x,e0.y,e0.z,e0.w,e1.x,e1.y,e1.z,e1.w};
            float qo[8] = {o0.x,o0.y,o0.z,o0.w,o1.x,o1.y,o1.z,o1.w};
            #pragma unroll
            for (int u = 0; u < 4; ++u) {
                const int off = 4 * sw(4*c8 + u);
                *(float4*)(qrow + off) =
                    make_float4(qe[2*u], qo[2*u], qe[2*u+1], qo[2*u+1]);
            }
        }

        // ---- k: same dance
        {
            float* krow = s_kk + rpb * SK;
            float4 e0 = *(const float4*)(Kk + be + 8*c8);
            float4 e1 = *(const float4*)(Kk + be + 8*c8 + 4);
            float4 o0 = *(const float4*)(Kk + bo + 8*c8);
            float4 o1 = *(const float4*)(Kk + bo + 8*c8 + 4);
            float ke[8] = {e0.x,e0.y,e0.z,e0.w,e1.x,e1.y,e1.z,e1.w};
            float ko[8] = {o0.x,o0.y,o0.z,o0.w,o1.x,o1.y,o1.z,o1.w};
            #pragma unroll
            for (int u = 0; u < 4; ++u) {
                const int off = 4 * sw(4*c8 + u);
                *(float4*)(krow + off) =
                    make_float4(ke[2*u], ko[2*u], ke[2*u+1], ko[2*u+1]);
            }
        }
    }
    __syncwarp();

    // ---------------- FIR correlation: 8 delays/lane, f32x2, 2 rows/lane -----
    const int s   = lane & 7;            // delay-octet sub-lane
    const int oct = lane >> 3;
    const int rp  = 4 * w + oct;         // row-pair owned by this octet
    const float* qq = s_qq + rp * SQ;
    const float* kk = s_kk + rp * SK;
    const int cb0 = 4 * s;               // chunk of element d0 = 8s

    #define LDQ(c) (*(const ulonglong2*)(qq + 4 * sw((c) & 31)))
    #define LDK(c) (*(const ulonglong2*)(kk + 4 * sw(c)))

    unsigned long long W[12], acc[8];
    #pragma unroll
    for (int u = 0; u < 4; ++u) {
        ulonglong2 tv = LDQ(cb0 + u);
        W[2*u] = tv.x; W[2*u + 1] = tv.y;
    }
    #pragma unroll
    for (int j = 0; j < 8; ++j) acc[j] = 0ull;

    #pragma unroll
    for (int blk = 0; blk < 16; ++blk) {
        ulonglong2 t0 = LDQ(cb0 + 2*blk + 4);
        ulonglong2 t1 = LDQ(cb0 + 2*blk + 5);
        W[8] = t0.x; W[9] = t0.y; W[10] = t1.x; W[11] = t1.y;
        ulonglong2 ka_ = LDK(2*blk);
        ulonglong2 kb_ = LDK(2*blk + 1);
        unsigned long long kp[4] = {ka_.x, ka_.y, kb_.x, kb_.y};
        #pragma unroll
        for (int tt = 0; tt < 4; ++tt)
            #pragma unroll
            for (int j = 0; j < 8; ++j)
                ffma2(acc[j], W[tt + j], kp[tt]);
        #pragma unroll
        for (int m = 0; m < 8; ++m) W[m] = W[m + 4];
    }
    __syncwarp();   // all q reads done before aliased corr staging

    // ---------------- split accumulators; stage corr into aliased q region ---
    // word e of corr row r lives at position e ^ (4*((r>>4)&1)) within the row
    // region: de-conflicts the transposed-read epilogue (rb vs rb+4 banks).
    float ex[8], od[8];
    #pragma unroll
    for (int j = 0; j < 8; ++j) {
        float2 f = *reinterpret_cast<float2*>(&acc[j]);
        ex[j] = f.x; od[j] = f.y;
    }
    const int x4c = ((rp >> 3) & 1) << 2;   // row 2rp and 2rp+1 share r>>4
    {
        float* ce = s_qq + rp * SQ;      // corr row 2rp   : words 0..63 (perm)
        float* co = ce + 68;             // corr row 2rp+1 : words 68..131 (perm)
        *(float4*)(ce + (( 8*s     ) ^ x4c)) = make_float4(ex[0], ex[1], ex[2], ex[3]);
        *(float4*)(ce + (( 8*s + 4 ) ^ x4c)) = make_float4(ex[4], ex[5], ex[6], ex[7]);
        *(float4*)(co + (( 8*s     ) ^ x4c)) = make_float4(od[0], od[1], od[2], od[3]);
        *(float4*)(co + (( 8*s + 4 ) ^ x4c)) = make_float4(od[4], od[5], od[6], od[7]);
    }

    // ---------------- top-4 + softmax + gather (packed-key argmax) -----------
    #pragma unroll
    for (int pass = 0; pass < 2; ++pass) {
        const int rowl = 8 * w + 2 * oct + pass;

        // pack: order-flipped value bits, low 6 bits = 63 - delay.
        // unsigned max == (value desc, then delay asc) == the jax tie rule.
        unsigned int kv[8];
        #pragma unroll
        for (int j = 0; j < 8; ++j) {
            float v = pass ? od[j] : ex[j];
            kv[j] = (fflip(v) & 0xFFFFFFC0u) | (unsigned int)(63 - (8*s + j));
        }

        float wv[4]; int wd[4];
        #pragma unroll
        for (int i = 0; i < 4; ++i) {
            unsigned int bk = max(max(max(kv[0], kv[1]), max(kv[2], kv[3])),
                                  max(max(kv[4], kv[5]), max(kv[6], kv[7])));
            #pragma unroll
            for (int off = 4; off; off >>= 1) {
                unsigned int ok = __shfl_xor_sync(0xffffffffu, bk, off);
                bk = max(bk, ok);
            }
            wd[i] = 63 - (int)(bk & 63u);
            wv[i] = funflip(bk & 0xFFFFFFC0u);   // quantized value (softmax only)
            if (i < 3) {
                #pragma unroll
                for (int j = 0; j < 8; ++j)
                    if (kv[j] == bk) kv[j] = 0u;   // remove winner (keys unique)
            }
        }

        float p[4];
        p[0] = 1.0f;                              // expf(0) == 1
        float z = 1.0f;
        #pragma unroll
        for (int i = 1; i < 4; ++i) { p[i] = __expf(wv[i] - wv[0]); z += p[i]; }
        const float rz = 1.f / z;

        // gather: lane owns e = 4s..4s+3 and 4s+32..4s+35
        //   octet addresses within an instruction are (4s + const): banks
        //   stride-4, all 8 lanes distinct -> conflict-free
        const float* vrow = s_v + rowl * SV;
        float om[8] = {0.f,0.f,0.f,0.f,0.f,0.f,0.f,0.f};
        #pragma unroll
        for (int i = 0; i < 4; ++i) {
            const float pi = p[i] * rz;
            const int baseA = 4*s + wd[i];
            const int baseB = baseA + 32;
            #pragma unroll
            for (int m = 0; m < 4; ++m)
                om[m]     = fmaf(pi, vrow[(baseA + m) & 63], om[m]);
            #pragma unroll
            for (int m = 0; m < 4; ++m)
                om[4 + m] = fmaf(pi, vrow[(baseB + m) & 63], om[4 + m]);
        }
        const size_t vb = ((size_t)bh * L_ + l0 + rowl) * (size_t)E_;
        *(float4*)(outV + vb + 4*s)      = make_float4(om[0], om[1], om[2], om[3]);
        *(float4*)(outV + vb + 4*s + 32) = make_float4(om[4], om[5], om[6], om[7]);
    }

    // ---------------- transposed corr write (vectorized over l) --------------
    // outC[b,e,h,l]: thread handles 4 consecutive l via STG.128.
    // Read side applies the same e^x4 permutation used at staging; lanes rb vs
    // rb+4 hit different banks (conflict-free).
    __syncthreads();
    float* outCb = outC + (((size_t)b * E_) * H_ + h) * (size_t)L_ + l0;
    #pragma unroll
    for (int it = 0; it < 4; ++it) {
        const int idx = t + NTHREADS * it;   // 0..511
        const int e   = idx >> 3;            // 0..63
        const int rb  = idx & 7;             // r = 4*rb .. 4*rb+3
        const int r0  = 4 * rb;
        const int x4r = ((rb >> 2) & 1) << 2;   // == ((r>>4)&1)<<2 for all 4 rows
        float4 val;
        val.x = s_qq[((r0    ) >> 1) * SQ + ((r0    ) & 1) * 68 + (e ^ x4r)];
        val.y = s_qq[((r0 + 1) >> 1) * SQ + ((r0 + 1) & 1) * 68 + (e ^ x4r)];
        val.z = s_qq[((r0 + 2) >> 1) * SQ + ((r0 + 2) & 1) * 68 + (e ^ x4r)];
        val.w = s_qq[((r0 + 3) >> 1) * SQ + ((r0 + 3) & 1) * 68 + (e ^ x4r)];
        *(float4*)(outCb + (size_t)e * ((size_t)H_ * L_) + 4 * rb) = val;
    }
}

extern "C" void kernel_launch(void* const* d_in, const int* in_sizes, int n_in,
                              void* d_out, int out_size)
{
    const float* Q = (const float*)d_in[0];
    const float* K = (const float*)d_in[1];
    const float* V = (const float*)d_in[2];
    float* outV = (float*)d_out;
    float* outC = outV + (size_t)B_ * H_ * L_ * E_;

    dim3 grid(L_ / ROWS, B_ * H_);
    ac_kernel<<<grid, NTHREADS>>>(Q, K, V, outV, outC);
}